// round 1
// baseline (speedup 1.0000x reference)
#include <cuda_runtime.h>

// Profile-HMM forward NLL + KLD, wavefront (anti-diagonal) formulation.
// B=512 batch elements, one warp each. Lane owns k = 2*lane+1, 2*lane+2.
// All log values kept in base-2 (pre-scaled by log2(e)) so logaddexp is
// fmax + lg2(1 + ex2(delta)) -- 2 MUFU ops, no scaling multiplies.

#define FULLMASK 0xffffffffu
#define LOG2E 1.4426950408889634f
#define LN2   0.69314718055994531f
#define NEG2  (-144.26950408889634f)   /* -100 * log2(e) */

__device__ float g_vb[512];

__device__ __forceinline__ float fexp2(float x) {
    float r; asm("ex2.approx.f32 %0, %1;" : "=f"(r) : "f"(x)); return r;
}
__device__ __forceinline__ float flog2(float x) {
    float r; asm("lg2.approx.f32 %0, %1;" : "=f"(r) : "f"(x)); return r;
}
// base-2 logaddexp: log2(2^x + 2^y)
__device__ __forceinline__ float laexp2(float x, float y) {
    float m = fmaxf(x, y);
    float d = fminf(x, y) - m;          // <= 0
    return m + flog2(1.0f + fexp2(d));
}

__global__ void __launch_bounds__(32) phmm_kernel(
    const int*   __restrict__ binput,    // (B, 256)
    const float* __restrict__ trans,     // (B, 65, 7)
    const float* __restrict__ emis,      // (B, 64, 4)
    const float* __restrict__ mus,       // (B, 16)
    const float* __restrict__ logvars)   // (B, 16)
{
    constexpr int L = 256;
    constexpr int K = 64;
    const int b    = blockIdx.x;
    const int lane = threadIdx.x;

    __shared__ int s_c[L];
    const int* bi = binput + b * L;
#pragma unroll
    for (int i = 0; i < L / 32; ++i) s_c[lane + 32 * i] = bi[lane + 32 * i];
    __syncthreads();

    const float* a  = trans + b * 65 * 7;
    const float* em = emis  + b * 64 * 4;

    const int k1 = 2 * lane + 1;                // slot1 owns k1, slot2 owns k1+1
    const float* r0 = a + (k1 - 1) * 7;         // transition row k1-1
    const float* r1 = r0 + 7;                   // row k1   (= row k2-1)
    const float* r2 = r1 + 7;                   // row k2

    // indices: M2M=0, M2I=1, M2D=2, I2M=3, I2I=4, D2M=5, D2D=6
    const float aMM1 = r0[0] * LOG2E, aMD1 = r0[2] * LOG2E;
    const float aIM1 = r0[3] * LOG2E, aDM1 = r0[5] * LOG2E, aDD1 = r0[6] * LOG2E;
    const float aMI1 = r1[1] * LOG2E, aII1 = r1[4] * LOG2E;
    const float aMM2 = r1[0] * LOG2E, aMD2 = r1[2] * LOG2E;
    const float aIM2 = r1[3] * LOG2E, aDM2 = r1[5] * LOG2E, aDD2 = r1[6] * LOG2E;
    const float aMI2 = r2[1] * LOG2E, aII2 = r2[4] * LOG2E;
    const float aMI0 = a[1]  * LOG2E, aII0 = a[4]  * LOG2E;   // row 0 (k=0 column)

    const float* eb1 = em + (k1 - 1) * 4;
    const float* eb2 = em + k1 * 4;
    const float e10 = eb1[0] * LOG2E, e11 = eb1[1] * LOG2E;
    const float e12 = eb1[2] * LOG2E, e13 = eb1[3] * LOG2E;
    const float e20 = eb2[0] * LOG2E, e21 = eb2[1] * LOG2E;
    const float e22 = eb2[2] * LOG2E, e23 = eb2[3] * LOG2E;

    // state registers: cur = this k's cell on diag t-1, prev = diag t-2
    float cM1 = NEG2, cI1 = NEG2, cD1 = NEG2, pM1 = NEG2, pI1 = NEG2, pD1 = NEG2;
    float cM2 = NEG2, cI2 = NEG2, cD2 = NEG2, pM2 = NEG2, pI2 = NEG2, pD2 = NEG2;
    // k=0 column (replicated on all lanes): M(0,0)=0 (base-2 of 1.0), I(0,0)=NEG
    float k0cM = 0.0f, k0cI = NEG2, k0pM = NEG2, k0pI = NEG2;

    int cprev = s_c[0];   // slot2's emission symbol == slot1's symbol one diag earlier

#pragma unroll 4
    for (int t = 1; t <= L + K; ++t) {
        // neighbor (k-1) values: lane-1's slot2; lane0's neighbor is the k=0 column
        float nM = __shfl_up_sync(FULLMASK, cM2, 1);   // M(l, k-1)   diag t-1
        float nD = __shfl_up_sync(FULLMASK, cD2, 1);   // D(l, k-1)   diag t-1
        float qM = __shfl_up_sync(FULLMASK, pM2, 1);   // M(l-1, k-1) diag t-2
        float qI = __shfl_up_sync(FULLMASK, pI2, 1);
        float qD = __shfl_up_sync(FULLMASK, pD2, 1);
        if (lane == 0) { nM = k0cM; nD = NEG2; qM = k0pM; qI = k0pI; qD = NEG2; }

        const int l1 = t - k1;
        const int l2 = l1 - 1;

        int ci = l1 - 1;
        ci = ci < 0 ? 0 : (ci > L - 1 ? L - 1 : ci);
        const int c1 = s_c[ci];
        const float e1 = (c1 & 2)    ? ((c1 & 1)    ? e13 : e12) : ((c1 & 1)    ? e11 : e10);
        const float e2 = (cprev & 2) ? ((cprev & 1) ? e23 : e22) : ((cprev & 1) ? e21 : e20);

        // ---- slot1: cell (l1, k1) ----
        float M1g = e1 + laexp2(laexp2(aMM1 + qM, aIM1 + qI), aDM1 + qD);
        float I1g = -2.0f + laexp2(aMI1 + cM1, aII1 + cI1);     // LOG_Q in base2 = -2
        float D1n = laexp2(aMD1 + nM, aDD1 + nD);               // same formula incl. l==0
        float M1n = (l1 == 0) ? NEG2 : M1g;
        float I1n = (l1 == 0) ? NEG2 : I1g;

        // ---- slot2: cell (l2, k2); neighbor is own (old) slot1 ----
        float M2g = e2 + laexp2(laexp2(aMM2 + pM1, aIM2 + pI1), aDM2 + pD1);
        float I2g = -2.0f + laexp2(aMI2 + cM2, aII2 + cI2);
        float D2n = laexp2(aMD2 + cM1, aDD2 + cD1);
        float M2n = (l2 == 0) ? NEG2 : M2g;
        float I2n = (l2 == 0) ? NEG2 : I2g;

        // ---- k=0 column, cell (t, 0): M=NEG for l>=1, D=NEG always ----
        float k0In = -2.0f + laexp2(aMI0 + k0cM, aII0 + k0cI);
        k0pM = k0cM; k0pI = k0cI; k0cM = NEG2; k0cI = k0In;

        // rotate only while the cell is in range (freeze afterwards so the
        // k+1 neighbor can still read the final cur/prev pair once)
        if ((unsigned)l2 <= (unsigned)L) {
            pM2 = cM2; pI2 = cI2; pD2 = cD2; cM2 = M2n; cI2 = I2n; cD2 = D2n;
        }
        if ((unsigned)l1 <= (unsigned)L) {
            pM1 = cM1; pI1 = cI1; pD1 = cD1; cM1 = M1n; cI1 = I1n; cD1 = D1n;
        }
        cprev = c1;
    }

    // lane 31 slot2 holds (M, I, D) at (L, K); broadcast to all lanes
    const float MF = __shfl_sync(FULLMASK, cM2, 31);
    const float IF = __shfl_sync(FULLMASK, cI2, 31);
    const float DF = __shfl_sync(FULLMASK, cD2, 31);
    const float x0 = MF + a[K * 7 + 0] * LOG2E;
    const float x1 = IF + a[K * 7 + 3] * LOG2E;
    const float x2 = DF + a[K * 7 + 5] * LOG2E;
    const float mx  = fmaxf(x0, fmaxf(x1, x2));
    const float lse = mx + flog2(fexp2(x0 - mx) + fexp2(x1 - mx) + fexp2(x2 - mx));
    const float nll = -lse * LN2;

    // KLD term: -0.5 * sum_e (1 + lv - mu^2 - exp(lv))
    float term = 0.0f;
    if (lane < 16) {
        const float mu = mus[b * 16 + lane];
        const float lv = logvars[b * 16 + lane];
        term = 1.0f + lv - mu * mu - expf(lv);
    }
#pragma unroll
    for (int o = 16; o > 0; o >>= 1) term += __shfl_xor_sync(FULLMASK, term, o);

    if (lane == 0) g_vb[b] = nll - 0.5f * term;
}

__global__ void __launch_bounds__(512) reduce_kernel(float* __restrict__ out) {
    __shared__ float sh[512];
    const int t = threadIdx.x;
    sh[t] = g_vb[t];
    __syncthreads();
#pragma unroll
    for (int s = 256; s >= 1; s >>= 1) {
        if (t < s) sh[t] += sh[t + s];
        __syncthreads();
    }
    if (t == 0) out[0] = sh[0] * (1.0f / 512.0f);
}

extern "C" void kernel_launch(void* const* d_in, const int* in_sizes, int n_in,
                              void* d_out, int out_size) {
    const int*   batch_input = (const int*)  d_in[0];
    const float* trans       = (const float*)d_in[1];
    const float* emisp       = (const float*)d_in[2];
    const float* mus         = (const float*)d_in[3];
    const float* logvars     = (const float*)d_in[4];
    (void)in_sizes; (void)n_in; (void)out_size;

    phmm_kernel<<<512, 32>>>(batch_input, trans, emisp, mus, logvars);
    reduce_kernel<<<1, 512>>>((float*)d_out);
}